// round 1
// baseline (speedup 1.0000x reference)
#include <cuda_runtime.h>

#define B_DIM    8
#define C_OUT    64
#define NK       7
#define GROUP_IN 4
#define C_IN     1792           // 64*4*7
#define L_DIM    4096
#define TILE     512
#define HALO     16             // covers |shift| <= 15, keeps 16B alignment
#define ROWW     (TILE + 2*HALO)   // 544 floats per staged row
#define NCH      (GROUP_IN * NK)   // 28 channels per c_out
#define THREADS  256

// out_o[b,co,t] = sum over 28 channels c of x[b,c,t - s_o(c)], zero-filled.
// s = (3 - idx%7)*5. We stage the 28 rows (with halo) in SMEM once and
// accumulate all three outputs, so x is read from DRAM exactly once.
__global__ __launch_bounds__(THREADS) void addshift_kernel(
    const float* __restrict__ x,
    const int*   __restrict__ si1,
    const int*   __restrict__ si2,
    const int*   __restrict__ si3,
    float*       __restrict__ out)
{
    extern __shared__ float sm[];          // [NCH][ROWW]
    __shared__ unsigned upk[NCH];          // packed row offsets: 3 x 8-bit fields

    const int tid = threadIdx.x;
    const int t0  = blockIdx.x * TILE;
    const int co  = blockIdx.y;
    const int b   = blockIdx.z;

    // --- per-block shift setup: offset into row = 16 - s = 1 + 5*(idx%7) ---
    if (tid < NCH) {
        int g = tid / NK, k = tid % NK;
        int c = g * (C_OUT * NK) + co * NK + k;
        unsigned o1 = 1u + 5u * (unsigned)(si1[c] % NK);
        unsigned o2 = 1u + 5u * (unsigned)(si2[c] % NK);
        unsigned o3 = 1u + 5u * (unsigned)(si3[c] % NK);
        upk[tid] = o1 | (o2 << 8) | (o3 << 16);
    }

    // --- stage 28 channel rows, window [t0-16, t0+528), float4 loads ---
    const int gstart = t0 - HALO;
    const bool interior = (gstart >= 0) && (gstart + ROWW <= L_DIM);
    const int NVEC = ROWW / 4;             // 136 float4 per row

    #pragma unroll 1
    for (int idx = tid; idx < NCH * NVEC; idx += THREADS) {
        int lc = idx / NVEC;
        int j4 = (idx - lc * NVEC) * 4;
        int g = lc / NK, k = lc - g * NK;
        int c = g * (C_OUT * NK) + co * NK + k;
        const float* src = x + ((size_t)b * C_IN + c) * L_DIM + gstart + j4;
        float4 v;
        if (interior) {
            v = *reinterpret_cast<const float4*>(src);   // 16B aligned: t0%512==0, j4%4==0
        } else {
            int gp = gstart + j4;
            v.x = (gp + 0 >= 0 && gp + 0 < L_DIM) ? src[0] : 0.f;
            v.y = (gp + 1 >= 0 && gp + 1 < L_DIM) ? src[1] : 0.f;
            v.z = (gp + 2 >= 0 && gp + 2 < L_DIM) ? src[2] : 0.f;
            v.w = (gp + 3 >= 0 && gp + 3 < L_DIM) ? src[3] : 0.f;
        }
        *reinterpret_cast<float4*>(&sm[lc * ROWW + j4]) = v;
    }
    __syncthreads();

    // --- accumulate: each thread owns t = t0+tid and t0+tid+256, all 3 outputs ---
    float a10 = 0.f, a11 = 0.f, a20 = 0.f, a21 = 0.f, a30 = 0.f, a31 = 0.f;
    #pragma unroll
    for (int lc = 0; lc < NCH; ++lc) {
        const float* row = sm + lc * ROWW + tid;
        unsigned p  = upk[lc];                 // broadcast LDS
        unsigned o1 =  p        & 255u;
        unsigned o2 = (p >> 8)  & 255u;
        unsigned o3 = (p >> 16) & 255u;
        a10 += row[o1];   a11 += row[o1 + 256];
        a20 += row[o2];   a21 += row[o2 + 256];
        a30 += row[o3];   a31 += row[o3 + 256];
    }

    const size_t OSZ   = (size_t)B_DIM * C_OUT * L_DIM;    // one output tensor
    const size_t obase = ((size_t)b * C_OUT + co) * L_DIM + t0 + tid;
    out[obase]               = a10;  out[obase + 256]           = a11;
    out[obase + OSZ]         = a20;  out[obase + OSZ + 256]     = a21;
    out[obase + 2 * OSZ]     = a30;  out[obase + 2 * OSZ + 256] = a31;
}

extern "C" void kernel_launch(void* const* d_in, const int* in_sizes, int n_in,
                              void* d_out, int out_size) {
    const float* x   = (const float*)d_in[0];
    const int*   si1 = (const int*)d_in[1];
    const int*   si2 = (const int*)d_in[2];
    const int*   si3 = (const int*)d_in[3];
    float* out = (float*)d_out;

    const int smem_bytes = NCH * ROWW * (int)sizeof(float);   // 60928
    cudaFuncSetAttribute(addshift_kernel,
                         cudaFuncAttributeMaxDynamicSharedMemorySize, smem_bytes);

    dim3 grid(L_DIM / TILE, C_OUT, B_DIM);   // (8, 64, 8) = 4096 blocks
    addshift_kernel<<<grid, THREADS, smem_bytes>>>(x, si1, si2, si3, out);
}

// round 2
// speedup vs baseline: 1.7658x; 1.7658x over previous
#include <cuda_runtime.h>
#include <cstdint>

#define B_DIM    8
#define C_OUT    64
#define NK       7
#define GROUP_IN 4
#define C_IN     1792              // 64*4*7
#define L_DIM    4096
#define TILE     512
#define HALO     16                // covers |shift| <= 15, keeps 16B alignment
#define ROWW     (TILE + 2*HALO)   // 544 floats per staged row
#define NCH      (GROUP_IN * NK)   // 28 channels per c_out
#define THREADS  512
#define NVEC     (ROWW / 4)        // 136 float4 chunks per row
#define NCHUNK   (NCH * NVEC)      // 3808 chunks per block

// 16B async copy global->shared with zero-fill when src_size == 0.
// Chunks are always fully in-bounds or fully out-of-bounds (boundaries at
// 0 and 4096 are multiples of 4 floats, chunk start gp ≡ 0 mod 4), so the
// zfill path implements the roll's zero-padding exactly.
__device__ __forceinline__ void cp_async16(uint32_t dst_smem, const void* src, int src_size) {
    asm volatile("cp.async.cg.shared.global [%0], [%1], 16, %2;\n"
                 :: "r"(dst_smem), "l"(src), "r"(src_size));
}

__global__ __launch_bounds__(THREADS, 3) void addshift_kernel(
    const float* __restrict__ x,
    const int*   __restrict__ si1,
    const int*   __restrict__ si2,
    const int*   __restrict__ si3,
    float*       __restrict__ out)
{
    extern __shared__ float sm[];          // [NCH][ROWW]
    __shared__ unsigned upk[NCH];          // packed row offsets: 3 x 8-bit fields

    const int tid = threadIdx.x;
    const int t0  = blockIdx.x * TILE;
    const int co  = blockIdx.y;
    const int b   = blockIdx.z;

    // --- per-block shift setup: offset into row = 16 - s = 1 + 5*(idx%7) ---
    if (tid < NCH) {
        int g = tid / NK, k = tid % NK;
        int c = g * (C_OUT * NK) + co * NK + k;
        unsigned o1 = 1u + 5u * (unsigned)(si1[c] % NK);
        unsigned o2 = 1u + 5u * (unsigned)(si2[c] % NK);
        unsigned o3 = 1u + 5u * (unsigned)(si3[c] % NK);
        upk[tid] = o1 | (o2 << 8) | (o3 << 16);
    }

    // --- stage 28 channel rows, window [t0-16, t0+528), via cp.async ---
    const int gstart = t0 - HALO;
    const uint32_t sm_base = (uint32_t)__cvta_generic_to_shared(sm);

    #pragma unroll
    for (int i = 0; i < (NCHUNK + THREADS - 1) / THREADS; ++i) {
        int idx = tid + i * THREADS;
        if (idx < NCHUNK) {
            int lc = idx / NVEC;
            int j4 = (idx - lc * NVEC) * 4;
            int g  = lc / NK, k = lc - g * NK;
            int c  = g * (C_OUT * NK) + co * NK + k;
            int gp = gstart + j4;
            const float* src = x + ((size_t)b * C_IN + c) * L_DIM + gp;
            int src_size = (gp >= 0 && gp < L_DIM) ? 16 : 0;
            cp_async16(sm_base + (uint32_t)(lc * ROWW + j4) * 4u, src, src_size);
        }
    }
    asm volatile("cp.async.commit_group;\n" ::: "memory");
    asm volatile("cp.async.wait_group 0;\n" ::: "memory");
    __syncthreads();

    // --- accumulate: each thread owns t = t0 + tid, all 3 outputs ---
    float a1 = 0.f, a2 = 0.f, a3 = 0.f;
    #pragma unroll
    for (int lc = 0; lc < NCH; ++lc) {
        const float* row = sm + lc * ROWW + tid;
        unsigned p  = upk[lc];                 // broadcast LDS, warp-uniform
        unsigned o1 =  p        & 255u;
        unsigned o2 = (p >> 8)  & 255u;
        unsigned o3 = (p >> 16) & 255u;
        a1 += row[o1];
        a2 += row[o2];
        a3 += row[o3];
    }

    const size_t OSZ   = (size_t)B_DIM * C_OUT * L_DIM;    // one output tensor
    const size_t obase = ((size_t)b * C_OUT + co) * L_DIM + t0 + tid;
    out[obase]           = a1;
    out[obase + OSZ]     = a2;
    out[obase + 2 * OSZ] = a3;
}

extern "C" void kernel_launch(void* const* d_in, const int* in_sizes, int n_in,
                              void* d_out, int out_size) {
    const float* x   = (const float*)d_in[0];
    const int*   si1 = (const int*)d_in[1];
    const int*   si2 = (const int*)d_in[2];
    const int*   si3 = (const int*)d_in[3];
    float* out = (float*)d_out;

    const int smem_bytes = NCH * ROWW * (int)sizeof(float);   // 60928
    cudaFuncSetAttribute(addshift_kernel,
                         cudaFuncAttributeMaxDynamicSharedMemorySize, smem_bytes);

    dim3 grid(L_DIM / TILE, C_OUT, B_DIM);   // (8, 64, 8) = 4096 blocks
    addshift_kernel<<<grid, THREADS, smem_bytes>>>(x, si1, si2, si3, out);
}

// round 3
// speedup vs baseline: 2.1090x; 1.1944x over previous
#include <cuda_runtime.h>
#include <cstdint>

#define B_DIM    8
#define C_OUT    64
#define NK       7
#define GROUP_IN 4
#define C_IN     1792              // 64*4*7
#define L_DIM    4096
#define TILE     512
#define HALO     16                // covers |shift| <= 15, 16B-aligned halo
#define ROWW     (TILE + 2*HALO)   // 544 floats per staged row
#define NCH      (GROUP_IN * NK)   // 28 channels per c_out
#define THREADS  512

// 16B async copy global->shared; src_size==0 -> zero-fill (implements the
// roll's zero padding: OOB regions are always whole 16B chunks).
__device__ __forceinline__ void cp_async16(uint32_t dst, const void* src, int sz) {
    asm volatile("cp.async.cg.shared.global [%0], [%1], 16, %2;\n"
                 :: "r"(dst), "l"(src), "r"(sz));
}

__global__ __launch_bounds__(THREADS, 3) void addshift_kernel(
    const float* __restrict__ x,
    const int*   __restrict__ si1,
    const int*   __restrict__ si2,
    const int*   __restrict__ si3,
    float*       __restrict__ out)
{
    extern __shared__ float sm[];      // [NCH][ROWW]
    __shared__ uint2 offs[NCH];        // pre-scaled smem byte offsets per channel

    const int tid = threadIdx.x;
    const int t0  = blockIdx.x * TILE;
    const int co  = blockIdx.y;
    const int b   = blockIdx.z;
    const int gstart = t0 - HALO;

    const uint32_t sm_base = (uint32_t)__cvta_generic_to_shared(sm);
    // base points at channel c0 = co*7 of this (b); row r adds (r/7)*448 + r%7 channels
    const float* base = x + ((size_t)b * C_IN + (size_t)co * NK) * L_DIM + gstart;

    // ---- interior staging: 7 passes x 4 rows x 128 chunks, always in-bounds ----
    // window [t0, t0+512) never crosses an edge, so no bounds check here.
    {
        const unsigned w2 = (unsigned)tid >> 7;                  // row-in-group 0..3
        const unsigned jj = ((unsigned)tid & 127u) * 4u + HALO;  // float idx in [16,524]
        const float* bsrc = base + jj;
        const uint32_t dst0 = sm_base + (w2 * ROWW + jj) * 4u;
        #pragma unroll
        for (int p = 0; p < 7; ++p) {
            unsigned r  = 4u * (unsigned)p + w2;                 // row 0..27
            unsigned rd = r / 7u, rm = r % 7u;                   // folded at unroll
            int crel = (int)(rd * 448u + rm) * L_DIM;            // channel offset (elems)
            cp_async16(dst0 + (uint32_t)p * (4u * ROWW * 4u), bsrc + crel, 16);
        }
    }
    // ---- halo staging: 28 rows x 8 chunks (4 front, 4 back), edge-guarded ----
    if (tid < NCH * 8) {
        unsigned lc = (unsigned)tid >> 3;
        unsigned h  = (unsigned)tid & 7u;
        unsigned j4 = (h < 4u) ? h * 4u : (TILE + h * 4u);       // 0..12, 528..540
        int gp = gstart + (int)j4;
        unsigned rd = lc / 7u, rm = lc % 7u;
        int crel = (int)(rd * 448u + rm) * L_DIM;
        int sz = (gp >= 0 && gp < L_DIM) ? 16 : 0;
        cp_async16(sm_base + (lc * ROWW + j4) * 4u, base + crel + (int)j4, sz);
    }
    asm volatile("cp.async.commit_group;\n" ::: "memory");

    // ---- offset table setup: overlaps cp.async DRAM latency ----
    // gather offset within row = 16 - shift = 1 + 5*(idx % 7); pre-scale to
    // bytes and fold in the row base lc*ROWW*4 (max 58876, fits u16 pair + u32).
    if (tid < NCH) {
        int g = tid / NK, k = tid % NK;
        int c = g * (C_OUT * NK) + co * NK + k;
        unsigned o1 = 1u + 5u * (unsigned)(si1[c] % NK);
        unsigned o2 = 1u + 5u * (unsigned)(si2[c] % NK);
        unsigned o3 = 1u + 5u * (unsigned)(si3[c] % NK);
        unsigned rb = (unsigned)(tid * ROWW) * 4u;
        offs[tid] = make_uint2((rb + o1 * 4u) | ((rb + o2 * 4u) << 16),
                                rb + o3 * 4u);
    }

    asm volatile("cp.async.wait_group 0;\n" ::: "memory");
    __syncthreads();

    // ---- accumulate: thread owns t = t0 + tid, all 3 outputs ----
    const char* smb = (const char*)sm + (size_t)((unsigned)tid * 4u);
    float a1 = 0.f, a2 = 0.f, a3 = 0.f;
    #pragma unroll
    for (int lc = 0; lc < NCH; ++lc) {
        uint2 o = offs[lc];                       // one LDS.64 broadcast
        a1 += *(const float*)(smb + (o.x & 0xffffu));
        a2 += *(const float*)(smb + (o.x >> 16));
        a3 += *(const float*)(smb + o.y);
    }

    const size_t OSZ = (size_t)B_DIM * C_OUT * L_DIM;     // one output tensor
    const size_t ob  = ((size_t)b * C_OUT + co) * L_DIM + t0 + tid;
    out[ob]           = a1;
    out[ob + OSZ]     = a2;
    out[ob + 2 * OSZ] = a3;
}

extern "C" void kernel_launch(void* const* d_in, const int* in_sizes, int n_in,
                              void* d_out, int out_size) {
    const float* x   = (const float*)d_in[0];
    const int*   si1 = (const int*)d_in[1];
    const int*   si2 = (const int*)d_in[2];
    const int*   si3 = (const int*)d_in[3];
    float* out = (float*)d_out;

    const int smem_bytes = NCH * ROWW * (int)sizeof(float);   // 60928
    cudaFuncSetAttribute(addshift_kernel,
                         cudaFuncAttributeMaxDynamicSharedMemorySize, smem_bytes);

    dim3 grid(L_DIM / TILE, C_OUT, B_DIM);   // (8, 64, 8) = 4096 blocks
    addshift_kernel<<<grid, THREADS, smem_bytes>>>(x, si1, si2, si3, out);
}